// round 9
// baseline (speedup 1.0000x reference)
#include <cuda_runtime.h>

#define BB 128   // batch
#define TT 128   // timesteps
#define NN 100   // subactors
#define HH 16    // hidden
#define SS 6     // state
#define GG 48    // 3*H gates

typedef unsigned long long ull;

// scratch: h states, laid out [n][t][gate][b]  (105 MB)
__device__ float g_h[(size_t)NN * TT * HH * BB];

// ---- packed f32x2 helpers ----
__device__ __forceinline__ ull ffma2(ull a, ull b, ull c) {
    ull d; asm("fma.rn.f32x2 %0, %1, %2, %3;" : "=l"(d) : "l"(a), "l"(b), "l"(c)); return d;
}
__device__ __forceinline__ ull pack2(float lo, float hi) {
    ull r; asm("mov.b64 %0, {%1, %2};" : "=l"(r) : "f"(lo), "f"(hi)); return r;
}
__device__ __forceinline__ float2 unpack2(ull v) {
    float2 f; asm("mov.b64 {%0, %1}, %2;" : "=f"(f.x), "=f"(f.y) : "l"(v)); return f;
}
__device__ __forceinline__ ull fadd2(ull a, ull b) {
    ull d; asm("add.rn.f32x2 %0, %1, %2;" : "=l"(d) : "l"(a), "l"(b)); return d;
}
// ---- fast activations (MUFU-based, ~1e-6 rel err) ----
__device__ __forceinline__ float fex2(float x) { float y; asm("ex2.approx.f32 %0, %1;" : "=f"(y) : "f"(x)); return y; }
__device__ __forceinline__ float frcp(float x) { float y; asm("rcp.approx.f32 %0, %1;" : "=f"(y) : "f"(x)); return y; }
__device__ __forceinline__ float fsigmoid(float x) {
    return frcp(1.0f + fex2(-1.4426950408889634f * x));
}
__device__ __forceinline__ float ftanh_(float x) {
    return fmaf(-2.0f, frcp(1.0f + fex2(2.8853900817779268f * x)), 1.0f);
}

// Dup-packed GRU weights: ulonglong2 = ((w_k,w_k),(w_{k+1},w_{k+1})) for the gate
// owned by lane l. Lane l (0..15) owns r-gate l, z-gate l, n-gate l.
struct __align__(16) SmemW1 {
    ulonglong2 whr2[8][16];
    ulonglong2 whz2[8][16];
    ulonglong2 whn2[8][16];
    ulonglong2 wir2[3][16];
    ulonglong2 wiz2[3][16];
    ulonglong2 win2[3][16];
};

// ================= Kernel 1: GRU recurrence only =================
__global__ void __launch_bounds__(64)
actor_gru_kernel(const float* __restrict__ x,
                 const float* __restrict__ Wih, const float* __restrict__ Whh,
                 const float* __restrict__ bih, const float* __restrict__ bhh)
{
    __shared__ SmemW1 sw;
    __shared__ __align__(16) ull hbuf[2][4][2][20];   // [parity][group][pair][k pad20]

    const int n   = blockIdx.x >> 3;
    const int qb  = blockIdx.x & 7;
    const int tid = threadIdx.x;
    const int l   = tid & 15;
    const int g   = tid >> 4;

    // ---------------- one-time weight staging ----------------
    {
        const float* Wh = Whh + n * GG * HH;
        const float* Wi = Wih + n * GG * SS;
        for (int i = tid; i < 8 * 16; i += 64) {
            int k2 = i >> 4, ll = i & 15;
            float a, b_;
            a = Wh[ll * HH + 2 * k2];        b_ = Wh[ll * HH + 2 * k2 + 1];
            sw.whr2[k2][ll] = make_ulonglong2(pack2(a, a), pack2(b_, b_));
            a = Wh[(16 + ll) * HH + 2 * k2]; b_ = Wh[(16 + ll) * HH + 2 * k2 + 1];
            sw.whz2[k2][ll] = make_ulonglong2(pack2(a, a), pack2(b_, b_));
            a = Wh[(32 + ll) * HH + 2 * k2]; b_ = Wh[(32 + ll) * HH + 2 * k2 + 1];
            sw.whn2[k2][ll] = make_ulonglong2(pack2(a, a), pack2(b_, b_));
        }
        for (int i = tid; i < 3 * 16; i += 64) {
            int k2 = i >> 4, ll = i & 15;
            float a, b_;
            a = Wi[ll * SS + 2 * k2];        b_ = Wi[ll * SS + 2 * k2 + 1];
            sw.wir2[k2][ll] = make_ulonglong2(pack2(a, a), pack2(b_, b_));
            a = Wi[(16 + ll) * SS + 2 * k2]; b_ = Wi[(16 + ll) * SS + 2 * k2 + 1];
            sw.wiz2[k2][ll] = make_ulonglong2(pack2(a, a), pack2(b_, b_));
            a = Wi[(32 + ll) * SS + 2 * k2]; b_ = Wi[(32 + ll) * SS + 2 * k2 + 1];
            sw.win2[k2][ll] = make_ulonglong2(pack2(a, a), pack2(b_, b_));
        }
        for (int i = tid; i < 4 * 2 * 20; i += 64)
            hbuf[0][i / 40][(i / 20) & 1][i % 20] = 0ULL;
    }
    // per-lane bias registers
    const float bi_r = bih[n * GG + l]      + bhh[n * GG + l];
    const float bi_z = bih[n * GG + 16 + l] + bhh[n * GG + 16 + l];
    const ull Rbr = pack2(bi_r, bi_r);
    const ull Rbz = pack2(bi_z, bi_z);
    const float bxn = bih[n * GG + 32 + l];
    const float bhn = bhh[n * GG + 32 + l];
    const ull Rbx = pack2(bxn, bxn);
    const ull Rbh = pack2(bhn, bhn);
    __syncthreads();

    // ---------------- per-group state: 4 sequences (2 packed pairs) ----------------
    const int b0 = qb * 16 + g * 4;
    const int xstride = NN * SS;
    const float* xps[4];
#pragma unroll
    for (int s = 0; s < 4; s++)
        xps[s] = x + (long long)(b0 + s) * TT * xstride + n * SS;

    ull own[2];
    own[0] = 0ULL; own[1] = 0ULL;

    float* hp0 = g_h + (((size_t)n * TT) * HH + l) * BB + b0;  // advances by HH*BB per t

    // prefetch t=0
    float2 pn[4][3];
#pragma unroll
    for (int s = 0; s < 4; s++) {
        const float2* px = reinterpret_cast<const float2*>(xps[s]);
        pn[s][0] = __ldg(px); pn[s][1] = __ldg(px + 1); pn[s][2] = __ldg(px + 2);
    }

#pragma unroll 1
    for (int t = 0; t < TT; t++) {
        const int par = t & 1;

        ull xp[2][6];
#pragma unroll
        for (int p = 0; p < 2; p++) {
#pragma unroll
            for (int j = 0; j < 3; j++) {
                xp[p][2 * j]     = pack2(pn[2 * p][j].x, pn[2 * p + 1][j].x);
                xp[p][2 * j + 1] = pack2(pn[2 * p][j].y, pn[2 * p + 1][j].y);
            }
        }
        {
            const bool more = (t + 1 < TT);
#pragma unroll
            for (int s = 0; s < 4; s++) {
                xps[s] += more ? xstride : 0;
                const float2* px = reinterpret_cast<const float2*>(xps[s]);
                pn[s][0] = __ldg(px); pn[s][1] = __ldg(px + 1); pn[s][2] = __ldg(px + 2);
            }
        }

        __syncwarp();   // order prev-iter hbuf writes vs this iter's reads

        ull ra[2] = { Rbr, Rbr }, za[2] = { Rbz, Rbz };
        ull xa[2] = { Rbx, Rbx }, ha[2] = { Rbh, Rbh };

#pragma unroll
        for (int k2 = 0; k2 < 8; k2++) {
            ulonglong2 wr = sw.whr2[k2][l], wz = sw.whz2[k2][l], wn = sw.whn2[k2][l];
            ulonglong2 h0 = *reinterpret_cast<const ulonglong2*>(&hbuf[par][g][0][2 * k2]);
            ulonglong2 h1 = *reinterpret_cast<const ulonglong2*>(&hbuf[par][g][1][2 * k2]);
            ra[0] = ffma2(h0.x, wr.x, ra[0]); ra[0] = ffma2(h0.y, wr.y, ra[0]);
            ra[1] = ffma2(h1.x, wr.x, ra[1]); ra[1] = ffma2(h1.y, wr.y, ra[1]);
            za[0] = ffma2(h0.x, wz.x, za[0]); za[0] = ffma2(h0.y, wz.y, za[0]);
            za[1] = ffma2(h1.x, wz.x, za[1]); za[1] = ffma2(h1.y, wz.y, za[1]);
            ha[0] = ffma2(h0.x, wn.x, ha[0]); ha[0] = ffma2(h0.y, wn.y, ha[0]);
            ha[1] = ffma2(h1.x, wn.x, ha[1]); ha[1] = ffma2(h1.y, wn.y, ha[1]);
        }
#pragma unroll
        for (int k2 = 0; k2 < 3; k2++) {
            ulonglong2 wr = sw.wir2[k2][l], wz = sw.wiz2[k2][l], wn = sw.win2[k2][l];
#pragma unroll
            for (int p = 0; p < 2; p++) {
                ull x0 = xp[p][2 * k2], x1 = xp[p][2 * k2 + 1];
                ra[p] = ffma2(x0, wr.x, ra[p]); ra[p] = ffma2(x1, wr.y, ra[p]);
                za[p] = ffma2(x0, wz.x, za[p]); za[p] = ffma2(x1, wz.y, za[p]);
                xa[p] = ffma2(x0, wn.x, xa[p]); xa[p] = ffma2(x1, wn.y, xa[p]);
            }
        }

#pragma unroll
        for (int p = 0; p < 2; p++) {
            float2 rv = unpack2(ra[p]);
            float r0 = fsigmoid(rv.x), r1 = fsigmoid(rv.y);
            float2 zv = unpack2(za[p]);
            float z0 = fsigmoid(zv.x), z1 = fsigmoid(zv.y);
            ull npre = ffma2(pack2(r0, r1), ha[p], xa[p]);
            float2 nv = unpack2(npre);
            float n0 = ftanh_(nv.x), n1 = ftanh_(nv.y);
            float2 hv = unpack2(own[p]);
            float h0 = fmaf(z0, hv.x - n0, n0);
            float h1 = fmaf(z1, hv.y - n1, n1);
            own[p] = pack2(h0, h1);
            hbuf[par ^ 1][g][p][l] = own[p];
            *reinterpret_cast<ull*>(hp0 + 2 * p) = own[p];
        }
        hp0 += (size_t)HH * BB;
    }
}

// ================= Kernel 2: MLP head (fully parallel) =================
__global__ void __launch_bounds__(256)
actor_mlp_kernel(const float* __restrict__ W1, const float* __restrict__ b1,
                 const float* __restrict__ W2, const float* __restrict__ b2,
                 const float* __restrict__ W3, const float* __restrict__ b3,
                 float* __restrict__ out)
{
    __shared__ __align__(16) ulonglong2 sw1[8][16];
    __shared__ __align__(16) ull yb[16][2][20];

    const int n   = blockIdx.x;
    const int tc  = blockIdx.y;
    const int tid = threadIdx.x;
    const int l   = tid & 15;
    const int g2  = tid >> 4;          // 16 groups, one t each
    const int t   = tc * 16 + g2;

    if (tid < 128) {
        int k2 = tid >> 4, ll = tid & 15;
        const float* W1N = W1 + n * HH * HH;
        float a = W1N[ll * HH + 2 * k2], b_ = W1N[ll * HH + 2 * k2 + 1];
        sw1[k2][ll] = make_ulonglong2(pack2(a, a), pack2(b_, b_));
    }
    const float b1s = b1[n * HH + l], b2s = b2[n * HH + l];
    const ull Rb1 = pack2(b1s, b1s), Rb2 = pack2(b2s, b2s);
    const float w3s = W3[n * HH + l];
    const ull Rw3 = pack2(w3s, w3s);
    const float Rb3 = b3[n];
    ulonglong2 Rw2[8];
    {
        const float* W2N = W2 + n * HH * HH + l * HH;
#pragma unroll
        for (int k2 = 0; k2 < 8; k2++) {
            float a = W2N[2 * k2], b_ = W2N[2 * k2 + 1];
            Rw2[k2] = make_ulonglong2(pack2(a, a), pack2(b_, b_));
        }
    }
    __syncthreads();

    const float* hbase = g_h + ((size_t)n * TT + t) * HH * BB;
    float* ob = out + (size_t)n * BB * TT + t;

#pragma unroll 1
    for (int b0 = 0; b0 < BB; b0 += 4) {
        // h rows: k -> ulonglong2 = (pair(b0,b0+1), pair(b0+2,b0+3)); direct LDG.128
        ulonglong2 hv[16];
#pragma unroll
        for (int k = 0; k < 16; k++)
            hv[k] = *reinterpret_cast<const ulonglong2*>(hbase + k * BB + b0);

        ull a1[2] = { Rb1, Rb1 };
#pragma unroll
        for (int k2 = 0; k2 < 8; k2++) {
            ulonglong2 w = sw1[k2][l];
            a1[0] = ffma2(hv[2 * k2].x, w.x, a1[0]);
            a1[0] = ffma2(hv[2 * k2 + 1].x, w.y, a1[0]);
            a1[1] = ffma2(hv[2 * k2].y, w.x, a1[1]);
            a1[1] = ffma2(hv[2 * k2 + 1].y, w.y, a1[1]);
        }
#pragma unroll
        for (int p = 0; p < 2; p++) {
            float2 v = unpack2(a1[p]);
            yb[g2][p][l] = pack2(fmaxf(v.x, 0.0f), fmaxf(v.y, 0.0f));
        }
        __syncwarp();

        ull a2[2] = { Rb2, Rb2 };
#pragma unroll
        for (int k2 = 0; k2 < 8; k2++) {
            ulonglong2 y0 = *reinterpret_cast<const ulonglong2*>(&yb[g2][0][2 * k2]);
            ulonglong2 y1 = *reinterpret_cast<const ulonglong2*>(&yb[g2][1][2 * k2]);
            a2[0] = ffma2(y0.x, Rw2[k2].x, a2[0]); a2[0] = ffma2(y0.y, Rw2[k2].y, a2[0]);
            a2[1] = ffma2(y1.x, Rw2[k2].x, a2[1]); a2[1] = ffma2(y1.y, Rw2[k2].y, a2[1]);
        }

        ull ps[2];
#pragma unroll
        for (int p = 0; p < 2; p++) {
            float2 v = unpack2(a2[p]);
            ps[p] = ffma2(pack2(fmaxf(v.x, 0.0f), fmaxf(v.y, 0.0f)), Rw3, 0ULL);
        }
#pragma unroll
        for (int off = 1; off < 16; off <<= 1) {
            ps[0] = fadd2(ps[0], __shfl_xor_sync(0xFFFFFFFFu, ps[0], off, 16));
            ps[1] = fadd2(ps[1], __shfl_xor_sync(0xFFFFFFFFu, ps[1], off, 16));
        }
        if (l < 4) {
            float2 p0 = unpack2(ps[0]), p1 = unpack2(ps[1]);
            float mys = (l == 0) ? p0.x : (l == 1) ? p0.y : (l == 2) ? p1.x : p1.y;
            ob[(size_t)(b0 + l) * TT] = fmaxf(mys + Rb3, 0.0f);
        }
        __syncwarp();
    }
}

extern "C" void kernel_launch(void* const* d_in, const int* in_sizes, int n_in,
                              void* d_out, int out_size)
{
    (void)in_sizes; (void)n_in; (void)out_size;
    const float* x   = (const float*)d_in[0];
    const float* Wih = (const float*)d_in[1];
    const float* Whh = (const float*)d_in[2];
    const float* bih = (const float*)d_in[3];
    const float* bhh = (const float*)d_in[4];
    const float* W1  = (const float*)d_in[5];
    const float* b1  = (const float*)d_in[6];
    const float* W2  = (const float*)d_in[7];
    const float* b2  = (const float*)d_in[8];
    const float* W3  = (const float*)d_in[9];
    const float* b3  = (const float*)d_in[10];
    float* out = (float*)d_out;

    actor_gru_kernel<<<NN * 8, 64>>>(x, Wih, Whh, bih, bhh);
    actor_mlp_kernel<<<dim3(NN, 8), 256>>>(W1, b1, W2, b2, W3, b3, out);
}